// round 12
// baseline (speedup 1.0000x reference)
#include <cuda_runtime.h>
#include <cuda_bf16.h>
#include <math.h>

// Problem constants
#define BB 2
#define SS 2048
#define DD 1024
#define HH 16
#define DK 64
#define ND (2*SS-1)          // 4095 relative-distance slots
#define MM (BB*SS)           // 4096 rows in the GEMMs

// Scratch (allocation-free: __device__ globals)
__device__ float g_q[BB*HH*SS*DK];     // [B,H,S,DK]
__device__ float g_k[BB*HH*SS*DK];
__device__ float g_v[BB*HH*SS*DK];     // [B,H,DK,S]  (TRANSPOSED by GEMM epilogue)
__device__ float g_ctx[BB*SS*HH*DK];   // [B,S,H*DK]
__device__ float g_bias[HH*ND];        // [H, rel+S-1]

// ---------------------------------------------------------------------------
// TF32 helpers
// ---------------------------------------------------------------------------
__device__ __forceinline__ unsigned f2tf(float x) {
    unsigned u;
    asm("cvt.rna.tf32.f32 %0, %1;" : "=r"(u) : "f"(x));
    return u;
}

__device__ __forceinline__ void mma8(float& d0, float& d1, float& d2, float& d3,
                                     unsigned a0, unsigned a1, unsigned a2, unsigned a3,
                                     unsigned b0, unsigned b1) {
    asm volatile("mma.sync.aligned.m16n8k8.row.col.f32.tf32.tf32.f32 "
                 "{%0,%1,%2,%3},{%4,%5,%6,%7},{%8,%9},{%0,%1,%2,%3};"
                 : "+f"(d0), "+f"(d1), "+f"(d2), "+f"(d3)
                 : "r"(a0), "r"(a1), "r"(a2), "r"(a3), "r"(b0), "r"(b1));
}

// Permutation for 64-wide K-dim: group cols by (c mod 4) so a thread's
// fragment words are contiguous; swizzle keeps LDS.128 conflict-free.
__device__ __forceinline__ int qperm(int c) {
    int cp = (c & 3) * 16 + (c >> 2);
    return cp ^ (((c & 3) >> 1) * 8);
}

// ---------------------------------------------------------------------------
// Bias precompute (correctness-proven)
// ---------------------------------------------------------------------------
__global__ void bias_precompute(const float* __restrict__ rel_bias) {
    int idx = blockIdx.x * blockDim.x + threadIdx.x;
    if (idx >= ND) return;
    int rel = idx - (SS - 1);        // rel = mem - ctx = j - i
    int n = -rel;
    int ret = (n < 0) ? 16 : 0;      // num_buckets//2 = 16
    n = (n < 0) ? -n : n;
    int bucket;
    if (n < 8) {
        bucket = n;
    } else {
        double v = log((double)n / 8.0) / log(16.0) * 8.0;
        int vi = 8 + (int)v;
        bucket = (vi < 15) ? vi : 15;
    }
    bucket += ret;
#pragma unroll
    for (int h = 0; h < HH; h++)
        g_bias[h * ND + idx] = rel_bias[bucket * HH + h];
}

// ---------------------------------------------------------------------------
// TF32 tensor-core GEMM (NT): C[m,n] = sum_k A[m,k] * B[n,k].
// 128x128x32 tile, 256 threads (8 warps, 2x4). Frag-vectorized permuted smem
// (stride 40, swizzle ^4*(r&1)). Two CTAs co-resident (launch_bounds(256,2)).
// MODE 0: row-major [M,N]. MODE 1: [B,H,S,DK] head split; z==2 (V) writes
// TRANSPOSED [B,H,DK,S] so the attention kernel's PV mma can fragment-
// vectorize V (same values, different layout).
// ---------------------------------------------------------------------------
template <int MODE>
__global__ __launch_bounds__(256, 2) void gemm_tf32(
        const float* __restrict__ A,
        const float* __restrict__ B0p, const float* __restrict__ B1p,
        const float* __restrict__ B2p,
        float* __restrict__ C0p, float* __restrict__ C1p, float* __restrict__ C2p) {
    __shared__ unsigned As[128][40];
    __shared__ unsigned Bs[128][40];
    const int t = threadIdx.x, lane = t & 31, g = lane >> 2, tig = lane & 3;
    const int w = t >> 5, wm = w >> 2, wn = w & 3;
    const int bm = blockIdx.y * 128, bn = blockIdx.x * 128;
    const int z = blockIdx.z;
    const float* Bm = (z == 0) ? B0p : (z == 1) ? B1p : B2p;
    float* C = (z == 0) ? C0p : (z == 1) ? C1p : C2p;

    float acc[4][4][4];
#pragma unroll
    for (int a = 0; a < 4; a++)
#pragma unroll
        for (int b = 0; b < 4; b++)
#pragma unroll
            for (int c = 0; c < 4; c++) acc[a][b][c] = 0.f;

    // staging indices: 1024 float4-chunks per matrix, 4 per thread
    int srow[4], scol[4];
#pragma unroll
    for (int i = 0; i < 4; i++) {
        int lin = t + 256 * i;
        srow[i] = lin >> 3;          // 0..127
        scol[i] = lin & 7;           // chunk index 0..7
    }

    const int sw = (g & 1) * 4;
    const int ca0 = (tig * 8) ^ sw;       // logical words 0-3 (kk = 0, 8)
    const int ca1 = (tig * 8 + 4) ^ sw;   // logical words 4-7 (kk = 16, 24)

    for (int k0 = 0; k0 < 1024; k0 += 32) {
        // batch all 8 global loads first (MLP=8), then convert+store
        float4 av[4], bv[4];
#pragma unroll
        for (int i = 0; i < 4; i++) {
            av[i] = *(const float4*)(A  + (size_t)(bm + srow[i]) * 1024 + k0 + scol[i] * 4);
            bv[i] = *(const float4*)(Bm + (size_t)(bn + srow[i]) * 1024 + k0 + scol[i] * 4);
        }
        __syncthreads();
#pragma unroll
        for (int i = 0; i < 4; i++) {
            const int r = srow[i];
            const int ap = scol[i] ^ ((r & 1) * 4);
            As[r][ap + 0]  = f2tf(av[i].x);
            As[r][ap + 8]  = f2tf(av[i].y);
            As[r][ap + 16] = f2tf(av[i].z);
            As[r][ap + 24] = f2tf(av[i].w);
            Bs[r][ap + 0]  = f2tf(bv[i].x);
            Bs[r][ap + 8]  = f2tf(bv[i].y);
            Bs[r][ap + 16] = f2tf(bv[i].z);
            Bs[r][ap + 24] = f2tf(bv[i].w);
        }
        __syncthreads();

        // B fragments for all 4 tn, all 4 kk-steps: 8 LDS.128
        uint4 Bf0[4], Bf1[4];
#pragma unroll
        for (int tn = 0; tn < 4; tn++) {
            const int c = wn * 32 + tn * 8 + g;    // c&1 == g&1
            Bf0[tn] = *(const uint4*)&Bs[c][ca0];
            Bf1[tn] = *(const uint4*)&Bs[c][ca1];
        }
#pragma unroll
        for (int tm = 0; tm < 4; tm++) {
            const int r = wm * 64 + tm * 16 + g;   // r&1 == g&1
            uint4 A00 = *(const uint4*)&As[r][ca0];
            uint4 A01 = *(const uint4*)&As[r][ca1];
            uint4 A10 = *(const uint4*)&As[r + 8][ca0];
            uint4 A11 = *(const uint4*)&As[r + 8][ca1];
#pragma unroll
            for (int tn = 0; tn < 4; tn++) {
                float* d = acc[tm][tn];
                mma8(d[0], d[1], d[2], d[3], A00.x, A10.x, A00.y, A10.y, Bf0[tn].x, Bf0[tn].y); // kk=0
                mma8(d[0], d[1], d[2], d[3], A00.z, A10.z, A00.w, A10.w, Bf0[tn].z, Bf0[tn].w); // kk=8
                mma8(d[0], d[1], d[2], d[3], A01.x, A11.x, A01.y, A11.y, Bf1[tn].x, Bf1[tn].y); // kk=16
                mma8(d[0], d[1], d[2], d[3], A01.z, A11.z, A01.w, A11.w, Bf1[tn].z, Bf1[tn].w); // kk=24
            }
        }
    }

#pragma unroll
    for (int tm = 0; tm < 4; tm++) {
#pragma unroll
        for (int tn = 0; tn < 4; tn++) {
            int m = bm + wm * 64 + tm * 16 + g;
            int n = bn + wn * 32 + tn * 8 + tig * 2;
            if (MODE == 0) {
                *(float2*)&C[(size_t)m * 1024 + n] =
                    make_float2(acc[tm][tn][0], acc[tm][tn][1]);
                *(float2*)&C[(size_t)(m + 8) * 1024 + n] =
                    make_float2(acc[tm][tn][2], acc[tm][tn][3]);
            } else {
                int h = n >> 6, dk = n & 63;
                int b0_ = m >> 11, s0 = m & 2047;    // m..m+8 stay in the same batch block
                if (z == 2) {
                    // V: transposed [B,H,DK,S]
                    size_t base = ((size_t)(b0_ * HH + h) * DK + dk) * SS;
                    C[base + s0]          = acc[tm][tn][0];
                    C[base + SS + s0]     = acc[tm][tn][1];
                    C[base + s0 + 8]      = acc[tm][tn][2];
                    C[base + SS + s0 + 8] = acc[tm][tn][3];
                } else {
                    *(float2*)&C[(((size_t)(b0_ * HH + h)) * SS + s0) * DK + dk] =
                        make_float2(acc[tm][tn][0], acc[tm][tn][1]);
                    *(float2*)&C[(((size_t)(b0_ * HH + h)) * SS + s0 + 8) * DK + dk] =
                        make_float2(acc[tm][tn][2], acc[tm][tn][3]);
                }
            }
        }
    }
}

// ---------------------------------------------------------------------------
// Flash attention with TF32 mma. CTA = 128 q-rows x (b,h); k in 64-col tiles.
// Q/K/V^T/P all live in qperm-permuted smem (stride 68): every mma fragment
// load is a conflict-free LDS.128. PV mirrors the S=QK^T structure exactly
// (P as A from [row][perm-col]; V^T as B, rows = dk). Softmax warp-local.
// Two CTAs co-reside (smem ~105KB x2 <= 227KB).
// ---------------------------------------------------------------------------
__global__ __launch_bounds__(256, 2) void attn_tf32() {
    extern __shared__ unsigned smu[];
    unsigned* Qs = smu;                   // [128][68]  permuted
    unsigned* Ps = Qs + 128 * 68;         // [128][68]  rows q, permuted cols c
    unsigned* Ks = Ps + 128 * 68;         // [64][68]   rows key, permuted cols d
    unsigned* Vt = Ks + 64 * 68;          // [64][68]   rows dk, permuted cols c
    float* bias_s = (float*)(Vt + 64 * 68);   // [192] (191 used)

    const int t = threadIdx.x, lane = t & 31, g = lane >> 2, tig = lane & 3;
    const int w = t >> 5;
    const int bh = blockIdx.y, h = bh & 15, b_ = bh >> 4;
    const int q0 = blockIdx.x * 128;
    const float* qg = g_q + (size_t)bh * SS * DK;
    const float* kg = g_k + (size_t)bh * SS * DK;
    const float* vg = g_v + (size_t)bh * SS * DK;   // [DK][S] per head

    // Stage Q [128][64] -> permuted Qs (persists the whole kernel)
#pragma unroll
    for (int i = 0; i < 8; i++) {
        int lin = t + 256 * i;            // 0..2047
        int r = lin >> 4, a = lin & 15;
        float4 v = *(const float4*)(qg + (size_t)(q0 + r) * DK + a * 4);
        unsigned* qr = &Qs[r * 68];
        qr[qperm(4 * a + 0)] = f2tf(v.x);
        qr[qperm(4 * a + 1)] = f2tf(v.y);
        qr[qperm(4 * a + 2)] = f2tf(v.z);
        qr[qperm(4 * a + 3)] = f2tf(v.w);
    }

    const int rb = w * 16;
    const int r0 = rb + g, r1 = rb + g + 8;

    const int fc[4] = { (tig * 16 + 0)  ^ ((tig >> 1) * 8),
                        (tig * 16 + 4)  ^ ((tig >> 1) * 8),
                        (tig * 16 + 8)  ^ ((tig >> 1) * 8),
                        (tig * 16 + 12) ^ ((tig >> 1) * 8) };

    float oacc[8][4];
#pragma unroll
    for (int tn = 0; tn < 8; tn++)
#pragma unroll
        for (int c = 0; c < 4; c++) oacc[tn][c] = 0.f;
    float m0 = -INFINITY, m1 = -INFINITY, l0 = 0.f, l1 = 0.f;

    for (int kt = 0; kt < SS / 64; kt++) {
        const int kb = kt * 64;
        __syncthreads();                  // prev Ks/Vt consumed (also orders Qs @kt=0)
#pragma unroll
        for (int i = 0; i < 4; i++) {
            int lin = t + 256 * i;        // 0..1023
            int row = lin >> 4, a = lin & 15;
            // K: row = key index, cols = d (contiguous in gmem)
            float4 kv = *(const float4*)(kg + (size_t)(kb + row) * DK + a * 4);
            unsigned* kr = &Ks[row * 68];
            kr[qperm(4 * a + 0)] = f2tf(kv.x);
            kr[qperm(4 * a + 1)] = f2tf(kv.y);
            kr[qperm(4 * a + 2)] = f2tf(kv.z);
            kr[qperm(4 * a + 3)] = f2tf(kv.w);
            // V^T: row = dk index, cols = key index (contiguous in gmem)
            float4 vv = *(const float4*)(vg + (size_t)row * SS + kb + a * 4);
            unsigned* vr = &Vt[row * 68];
            vr[qperm(4 * a + 0)] = f2tf(vv.x);
            vr[qperm(4 * a + 1)] = f2tf(vv.y);
            vr[qperm(4 * a + 2)] = f2tf(vv.z);
            vr[qperm(4 * a + 3)] = f2tf(vv.w);
        }
        if (t < 191)                      // rel in [-2047, 2047] exactly; no clamp needed
            bias_s[t] = g_bias[h * ND + (kb - q0 - 127 + t) + (SS - 1)];
        __syncthreads();

        // Q fragments for this tile (8 LDS.128, conflict-free)
        uint4 Aq0[4], Aq1[4];
#pragma unroll
        for (int u = 0; u < 4; u++) {
            Aq0[u] = *(const uint4*)&Qs[r0 * 68 + fc[u]];
            Aq1[u] = *(const uint4*)&Qs[r1 * 68 + fc[u]];
        }

        // S = Q @ K^T  (warp strip: 16 rows x 64 cols)
        float sv[8][4];
#pragma unroll
        for (int tn = 0; tn < 8; tn++)
#pragma unroll
            for (int c = 0; c < 4; c++) sv[tn][c] = 0.f;

#pragma unroll
        for (int tn = 0; tn < 8; tn++) {
            const int krow = (tn * 8 + g) * 68;
            float* d = sv[tn];
#pragma unroll
            for (int u = 0; u < 4; u++) {
                uint4 Kf = *(const uint4*)&Ks[krow + fc[u]];
                mma8(d[0], d[1], d[2], d[3],
                     Aq0[u].x, Aq1[u].x, Aq0[u].y, Aq1[u].y, Kf.x, Kf.y);  // kk = 16u
                mma8(d[0], d[1], d[2], d[3],
                     Aq0[u].z, Aq1[u].z, Aq0[u].w, Aq1[u].w, Kf.z, Kf.w);  // kk = 16u+8
            }
        }

        // bias + warp-local online softmax (rows r0, r1)
        float mx0 = -INFINITY, mx1 = -INFINITY;
#pragma unroll
        for (int tn = 0; tn < 8; tn++) {
            int c = tn * 8 + tig * 2;
            sv[tn][0] += bias_s[c - r0 + 127];
            sv[tn][1] += bias_s[c + 1 - r0 + 127];
            sv[tn][2] += bias_s[c - r1 + 127];
            sv[tn][3] += bias_s[c + 1 - r1 + 127];
            mx0 = fmaxf(mx0, fmaxf(sv[tn][0], sv[tn][1]));
            mx1 = fmaxf(mx1, fmaxf(sv[tn][2], sv[tn][3]));
        }
        mx0 = fmaxf(mx0, __shfl_xor_sync(0xffffffffu, mx0, 1));
        mx0 = fmaxf(mx0, __shfl_xor_sync(0xffffffffu, mx0, 2));
        mx1 = fmaxf(mx1, __shfl_xor_sync(0xffffffffu, mx1, 1));
        mx1 = fmaxf(mx1, __shfl_xor_sync(0xffffffffu, mx1, 2));
        const float mn0 = fmaxf(m0, mx0), mn1 = fmaxf(m1, mx1);
        const float sc0 = __expf(m0 - mn0), sc1 = __expf(m1 - mn1);
        float s0 = 0.f, s1 = 0.f;
#pragma unroll
        for (int tn = 0; tn < 8; tn++) {
            sv[tn][0] = __expf(sv[tn][0] - mn0);
            sv[tn][1] = __expf(sv[tn][1] - mn0);
            sv[tn][2] = __expf(sv[tn][2] - mn1);
            sv[tn][3] = __expf(sv[tn][3] - mn1);
            s0 += sv[tn][0] + sv[tn][1];
            s1 += sv[tn][2] + sv[tn][3];
        }
        s0 += __shfl_xor_sync(0xffffffffu, s0, 1);
        s0 += __shfl_xor_sync(0xffffffffu, s0, 2);
        s1 += __shfl_xor_sync(0xffffffffu, s1, 1);
        s1 += __shfl_xor_sync(0xffffffffu, s1, 2);
        l0 = l0 * sc0 + s0; l1 = l1 * sc1 + s1;
        m0 = mn0; m1 = mn1;

        // rescale O, spill P as [row][perm-col] (warp-private rows).
        // pc computed with the REAL qperm (R11 bug: linearized form broke
        // for tn >= 4 because the ^8 is not an addition when 2tn+(tig>>1) >= 8).
#pragma unroll
        for (int tn = 0; tn < 8; tn++) {
            oacc[tn][0] *= sc0; oacc[tn][1] *= sc0;
            oacc[tn][2] *= sc1; oacc[tn][3] *= sc1;
            const int pc = qperm(tn * 8 + tig * 2);   // qperm(c+1) = pc + 16
            Ps[r0 * 68 + pc]      = f2tf(sv[tn][0]);
            Ps[r0 * 68 + pc + 16] = f2tf(sv[tn][1]);
            Ps[r1 * 68 + pc]      = f2tf(sv[tn][2]);
            Ps[r1 * 68 + pc + 16] = f2tf(sv[tn][3]);
        }
        __syncwarp();

        // O += P @ V  (mirror of S-mma: P = A, V^T = B; all LDS.128)
        uint4 Pa0[4], Pa1[4];
#pragma unroll
        for (int u = 0; u < 4; u++) {
            Pa0[u] = *(const uint4*)&Ps[r0 * 68 + fc[u]];
            Pa1[u] = *(const uint4*)&Ps[r1 * 68 + fc[u]];
        }
#pragma unroll
        for (int tn = 0; tn < 8; tn++) {
            const int vrow = (tn * 8 + g) * 68;
            float* d = oacc[tn];
#pragma unroll
            for (int u = 0; u < 4; u++) {
                uint4 Vf = *(const uint4*)&Vt[vrow + fc[u]];
                mma8(d[0], d[1], d[2], d[3],
                     Pa0[u].x, Pa1[u].x, Pa0[u].y, Pa1[u].y, Vf.x, Vf.y);  // kk = 16u
                mma8(d[0], d[1], d[2], d[3],
                     Pa0[u].z, Pa1[u].z, Pa0[u].w, Pa1[u].w, Vf.z, Vf.w);  // kk = 16u+8
            }
        }
    }

    // Normalize + write ctx in [B, S, H*DK]
    const float i0 = 1.f / l0, i1 = 1.f / l1;
    float* op = g_ctx + ((size_t)b_ * SS + q0) * DD + h * DK;
#pragma unroll
    for (int tn = 0; tn < 8; tn++) {
        int n = tn * 8 + tig * 2;
        *(float2*)&op[(size_t)(rb + g) * DD + n] =
            make_float2(oacc[tn][0] * i0, oacc[tn][1] * i0);
        *(float2*)&op[(size_t)(rb + g + 8) * DD + n] =
            make_float2(oacc[tn][2] * i1, oacc[tn][3] * i1);
    }
}

// ---------------------------------------------------------------------------
extern "C" void kernel_launch(void* const* d_in, const int* in_sizes, int n_in,
                              void* d_out, int out_size) {
    const float* x        = (const float*)d_in[0];
    const float* q_w      = (const float*)d_in[1];
    const float* k_w      = (const float*)d_in[2];
    const float* v_w      = (const float*)d_in[3];
    const float* o_w      = (const float*)d_in[4];
    const float* rel_bias = (const float*)d_in[5];

    float *qp, *kp, *vp, *cp;
    cudaGetSymbolAddress((void**)&qp, g_q);
    cudaGetSymbolAddress((void**)&kp, g_k);
    cudaGetSymbolAddress((void**)&vp, g_v);
    cudaGetSymbolAddress((void**)&cp, g_ctx);

    bias_precompute<<<(ND + 255) / 256, 256>>>(rel_bias);

    // Fused QKV projection: grid.z picks the weight/output pair (z=2 -> V^T)
    gemm_tf32<1><<<dim3(8, 32, 3), 256>>>(x, q_w, k_w, v_w, qp, kp, vp);

    const size_t smem = (size_t)(128 * 68 + 128 * 68 + 64 * 68 + 64 * 68 + 192) * 4;
    cudaFuncSetAttribute(attn_tf32, cudaFuncAttributeMaxDynamicSharedMemorySize, (int)smem);
    attn_tf32<<<dim3(SS / 128, BB * HH), 256, smem>>>();

    // Output projection
    gemm_tf32<0><<<dim3(8, 32, 1), 256>>>(cp, o_w, o_w, o_w,
                                          (float*)d_out, (float*)d_out, (float*)d_out);
}

// round 14
// speedup vs baseline: 1.0267x; 1.0267x over previous
#include <cuda_runtime.h>
#include <cuda_bf16.h>
#include <math.h>

// Problem constants
#define BB 2
#define SS 2048
#define DD 1024
#define HH 16
#define DK 64
#define ND (2*SS-1)          // 4095 relative-distance slots
#define MM (BB*SS)           // 4096 rows in the GEMMs

// Scratch (allocation-free: __device__ globals)
__device__ float    g_q[BB*HH*SS*DK];     // [B,H,S,DK]
__device__ float    g_k[BB*HH*SS*DK];
__device__ float    g_v[BB*HH*SS*DK];     // [B,H,S,DK]
__device__ unsigned g_xp[MM*DD];          // x, tf32 bits, perm32 blocks
__device__ unsigned g_wq[DD*DD];          // weights, tf32 bits, perm32 blocks
__device__ unsigned g_wk[DD*DD];
__device__ unsigned g_wv[DD*DD];
__device__ unsigned g_wo[DD*DD];
__device__ unsigned g_ctxp[MM*DD];        // attention output, tf32 bits, perm32
__device__ float    g_bias[HH*ND];        // [H, rel+S-1]

// ---------------------------------------------------------------------------
// TF32 helpers
// ---------------------------------------------------------------------------
__device__ __forceinline__ unsigned f2tf(float x) {
    unsigned u;
    asm("cvt.rna.tf32.f32 %0, %1;" : "=r"(u) : "f"(x));
    return u;
}

__device__ __forceinline__ void mma8(float& d0, float& d1, float& d2, float& d3,
                                     unsigned a0, unsigned a1, unsigned a2, unsigned a3,
                                     unsigned b0, unsigned b1) {
    asm volatile("mma.sync.aligned.m16n8k8.row.col.f32.tf32.tf32.f32 "
                 "{%0,%1,%2,%3},{%4,%5,%6,%7},{%8,%9},{%0,%1,%2,%3};"
                 : "+f"(d0), "+f"(d1), "+f"(d2), "+f"(d3)
                 : "r"(a0), "r"(a1), "r"(a2), "r"(a3), "r"(b0), "r"(b1));
}

// Permutation for the attention's 64-wide K-dim smem tiles.
__device__ __forceinline__ int qperm(int c) {
    int cp = (c & 3) * 16 + (c >> 2);
    return cp ^ (((c & 3) >> 1) * 8);
}

__device__ __forceinline__ unsigned smem_u32(const void* p) {
    unsigned r;
    asm("{ .reg .u64 t; cvta.to.shared.u64 t, %1; cvt.u32.u64 %0, t; }"
        : "=r"(r) : "l"(p));
    return r;
}

__device__ __forceinline__ void cpa16(unsigned dst, const void* src) {
    asm volatile("cp.async.cg.shared.global [%0], [%1], 16;" :: "r"(dst), "l"(src));
}

// ---------------------------------------------------------------------------
// Prep: convert fp32 -> tf32 bits, stored permuted within each 32-col block:
// dst word (c&~31) + 8*(k&3) + ((k&31)>>2) holds src value k. One float4/thread.
// ---------------------------------------------------------------------------
__global__ void prep_permute(const float* __restrict__ src, unsigned* __restrict__ dst) {
    int tid = blockIdx.x * 256 + threadIdx.x;   // one float4 per thread
    int row = tid >> 8, c = (tid & 255) * 4;
    float4 v = *(const float4*)(src + (size_t)row * 1024 + c);
    unsigned* d = dst + (size_t)row * 1024 + (c & ~31) + ((c & 31) >> 2);
    d[0]  = f2tf(v.x);
    d[8]  = f2tf(v.y);
    d[16] = f2tf(v.z);
    d[24] = f2tf(v.w);
}

// ---------------------------------------------------------------------------
// Bias precompute (correctness-proven)
// ---------------------------------------------------------------------------
__global__ void bias_precompute(const float* __restrict__ rel_bias) {
    int idx = blockIdx.x * blockDim.x + threadIdx.x;
    if (idx >= ND) return;
    int rel = idx - (SS - 1);        // rel = mem - ctx = j - i
    int n = -rel;
    int ret = (n < 0) ? 16 : 0;      // num_buckets//2 = 16
    n = (n < 0) ? -n : n;
    int bucket;
    if (n < 8) {
        bucket = n;
    } else {
        double v = log((double)n / 8.0) / log(16.0) * 8.0;
        int vi = 8 + (int)v;
        bucket = (vi < 15) ? vi : 15;
    }
    bucket += ret;
#pragma unroll
    for (int h = 0; h < HH; h++)
        g_bias[h * ND + idx] = rel_bias[bucket * HH + h];
}

// ---------------------------------------------------------------------------
// TF32 tensor-core GEMM (NT) over PRE-PERMUTED tf32 inputs.
// C[m,n] = sum_k A[m,k]*B[n,k]. 128x128x32 tile, 256 threads (8 warps, 2x4).
// Staging: cp.async 16B chunks, double-buffered (2 stages); gmem chunk j of a
// row's 32-block lands at smem chunk j^(r&1) (row stride 40 words), which
// reproduces exactly the proven fragment addressing ca = tig*8 ^ 4(g&1).
// No cvt, no LDG->STS register path in the hot loop.
// MODE 0: C row-major [M,N]; MODE 1: C as [B,H,S,DK] (fused head split).
// ---------------------------------------------------------------------------
template <int MODE>
__global__ __launch_bounds__(256, 2) void gemm_tf32(
        const unsigned* __restrict__ A,
        const unsigned* __restrict__ B0p, const unsigned* __restrict__ B1p,
        const unsigned* __restrict__ B2p,
        float* __restrict__ C0p, float* __restrict__ C1p, float* __restrict__ C2p) {
    extern __shared__ unsigned smem[];      // [2 stages][A|B][128*40]
    const int STG = 128 * 40;
    const int t = threadIdx.x, lane = t & 31, g = lane >> 2, tig = lane & 3;
    const int w = t >> 5, wm = w >> 2, wn = w & 3;
    const int bm = blockIdx.y * 128, bn = blockIdx.x * 128;
    const int z = blockIdx.z;
    const unsigned* Bm = (z == 0) ? B0p : (z == 1) ? B1p : B2p;
    float* C = (z == 0) ? C0p : (z == 1) ? C1p : C2p;

    float acc[4][4][4];
#pragma unroll
    for (int a = 0; a < 4; a++)
#pragma unroll
        for (int b = 0; b < 4; b++)
#pragma unroll
            for (int c = 0; c < 4; c++) acc[a][b][c] = 0.f;

    // staging: 1024 16B-chunks per matrix, 4 per thread
    int srow[4], sj[4]; unsigned sdo[4];
#pragma unroll
    for (int i = 0; i < 4; i++) {
        int lin = t + 256 * i;
        srow[i] = lin >> 3;
        sj[i]   = lin & 7;
        sdo[i]  = (unsigned)(srow[i] * 40 + ((sj[i] ^ (srow[i] & 1)) * 4)) * 4u;
    }
    const unsigned smb = smem_u32(smem);

#define STAGE(tile, st) do {                                                    \
        unsigned ab = smb + (unsigned)(st) * 2u * STG * 4u;                     \
        unsigned bb = ab + (unsigned)STG * 4u;                                  \
        int kk0 = (tile) * 32;                                                  \
        _Pragma("unroll")                                                       \
        for (int i = 0; i < 4; i++) {                                           \
            cpa16(ab + sdo[i], A  + (size_t)(bm + srow[i]) * 1024 + kk0 + sj[i] * 4); \
            cpa16(bb + sdo[i], Bm + (size_t)(bn + srow[i]) * 1024 + kk0 + sj[i] * 4); \
        }                                                                       \
        asm volatile("cp.async.commit_group;");                                 \
    } while (0)

    STAGE(0, 0);
    STAGE(1, 1);

    const int sw  = (g & 1) * 4;
    const int ca0 = (tig * 8) ^ sw;       // words for kk = 0, 8
    const int ca1 = (tig * 8 + 4) ^ sw;   // words for kk = 16, 24

    for (int it = 0; it < 32; it++) {
        if (it < 31) asm volatile("cp.async.wait_group 1;" ::: "memory");
        else         asm volatile("cp.async.wait_group 0;" ::: "memory");
        __syncthreads();
        const unsigned* As = smem + (it & 1) * 2 * STG;
        const unsigned* Bs = As + STG;

        uint4 Bf0[4], Bf1[4];
#pragma unroll
        for (int tn = 0; tn < 4; tn++) {
            const int c = wn * 32 + tn * 8 + g;    // c&1 == g&1
            Bf0[tn] = *(const uint4*)&Bs[c * 40 + ca0];
            Bf1[tn] = *(const uint4*)&Bs[c * 40 + ca1];
        }
#pragma unroll
        for (int tm = 0; tm < 4; tm++) {
            const int r = wm * 64 + tm * 16 + g;   // r&1 == g&1
            uint4 A00 = *(const uint4*)&As[r * 40 + ca0];
            uint4 A01 = *(const uint4*)&As[r * 40 + ca1];
            uint4 A10 = *(const uint4*)&As[(r + 8) * 40 + ca0];
            uint4 A11 = *(const uint4*)&As[(r + 8) * 40 + ca1];
#pragma unroll
            for (int tn = 0; tn < 4; tn++) {
                float* d = acc[tm][tn];
                mma8(d[0], d[1], d[2], d[3], A00.x, A10.x, A00.y, A10.y, Bf0[tn].x, Bf0[tn].y); // kk=0
                mma8(d[0], d[1], d[2], d[3], A00.z, A10.z, A00.w, A10.w, Bf0[tn].z, Bf0[tn].w); // kk=8
                mma8(d[0], d[1], d[2], d[3], A01.x, A11.x, A01.y, A11.y, Bf1[tn].x, Bf1[tn].y); // kk=16
                mma8(d[0], d[1], d[2], d[3], A01.z, A11.z, A01.w, A11.w, Bf1[tn].z, Bf1[tn].w); // kk=24
            }
        }
        __syncthreads();
        if (it < 30) STAGE(it + 2, it & 1);
    }
#undef STAGE

#pragma unroll
    for (int tm = 0; tm < 4; tm++) {
#pragma unroll
        for (int tn = 0; tn < 4; tn++) {
            int m = bm + wm * 64 + tm * 16 + g;
            int n = bn + wn * 32 + tn * 8 + tig * 2;
            float2 v0 = make_float2(acc[tm][tn][0], acc[tm][tn][1]);
            float2 v1 = make_float2(acc[tm][tn][2], acc[tm][tn][3]);
            if (MODE == 0) {
                *(float2*)&C[(size_t)m * 1024 + n] = v0;
                *(float2*)&C[(size_t)(m + 8) * 1024 + n] = v1;
            } else {
                int h = n >> 6, dk = n & 63;
                int b0_ = m >> 11, s0 = m & 2047;
                *(float2*)&C[(((size_t)(b0_ * HH + h)) * SS + s0) * DK + dk] = v0;
                *(float2*)&C[(((size_t)(b0_ * HH + h)) * SS + s0 + 8) * DK + dk] = v1;
            }
        }
    }
}

// ---------------------------------------------------------------------------
// Flash attention with TF32 mma — the proven R10 structure (620.7us path).
// Only change: the epilogue writes ctx as PERMUTED tf32 bits (g_ctxp) so the
// output-projection GEMM can consume it via cp.async with no conversion.
// ---------------------------------------------------------------------------
__global__ __launch_bounds__(256, 2) void attn_tf32() {
    extern __shared__ unsigned smu[];
    unsigned* Qs = smu;                   // [128][68]  permuted
    unsigned* Ps = Qs + 128 * 68;         // [64][140]
    unsigned* Ks = Ps + 64 * 140;         // [64][68]   permuted
    unsigned* Vs = Ks + 64 * 68;          // [64][72]   row-major
    float* bias_s = (float*)(Vs + 64 * 72);   // [192] (191 used)

    const int t = threadIdx.x, lane = t & 31, g = lane >> 2, tig = lane & 3;
    const int w = t >> 5;
    const int bh = blockIdx.y, h = bh & 15, b_ = bh >> 4;
    const int q0 = blockIdx.x * 128;
    const float* qg = g_q + (size_t)bh * SS * DK;
    const float* kg = g_k + (size_t)bh * SS * DK;
    const float* vg = g_v + (size_t)bh * SS * DK;

    // Stage Q [128][64] -> permuted Qs (persists the whole kernel)
#pragma unroll
    for (int i = 0; i < 8; i++) {
        int lin = t + 256 * i;            // 0..2047
        int r = lin >> 4, a = lin & 15;
        float4 v = *(const float4*)(qg + (size_t)(q0 + r) * DK + a * 4);
        unsigned* qr = &Qs[r * 68];
        qr[qperm(4 * a + 0)] = f2tf(v.x);
        qr[qperm(4 * a + 1)] = f2tf(v.y);
        qr[qperm(4 * a + 2)] = f2tf(v.z);
        qr[qperm(4 * a + 3)] = f2tf(v.w);
    }

    const int rb = w * 16;
    const int r0 = rb + g, r1 = rb + g + 8;

    const int fc[4] = { (tig * 16 + 0)  ^ ((tig >> 1) * 8),
                        (tig * 16 + 4)  ^ ((tig >> 1) * 8),
                        (tig * 16 + 8)  ^ ((tig >> 1) * 8),
                        (tig * 16 + 12) ^ ((tig >> 1) * 8) };

    float oacc[8][4];
#pragma unroll
    for (int tn = 0; tn < 8; tn++)
#pragma unroll
        for (int c = 0; c < 4; c++) oacc[tn][c] = 0.f;
    float m0 = -INFINITY, m1 = -INFINITY, l0 = 0.f, l1 = 0.f;

    for (int kt = 0; kt < SS / 64; kt++) {
        const int kb = kt * 64;
        __syncthreads();                  // prev Ks/Vs/Ps consumed (also orders Qs @kt=0)
#pragma unroll
        for (int i = 0; i < 4; i++) {
            int lin = t + 256 * i;        // 0..1023
            int c = lin >> 4, a = lin & 15;
            float4 kv = *(const float4*)(kg + (size_t)(kb + c) * DK + a * 4);
            float4 vv = *(const float4*)(vg + (size_t)(kb + c) * DK + a * 4);
            unsigned* kr = &Ks[c * 68];
            kr[qperm(4 * a + 0)] = f2tf(kv.x);
            kr[qperm(4 * a + 1)] = f2tf(kv.y);
            kr[qperm(4 * a + 2)] = f2tf(kv.z);
            kr[qperm(4 * a + 3)] = f2tf(kv.w);
            *(uint4*)&Vs[c * 72 + a * 4] =
                make_uint4(f2tf(vv.x), f2tf(vv.y), f2tf(vv.z), f2tf(vv.w));
        }
        if (t < 191)                      // rel in [-2047, 2047] exactly; no clamp needed
            bias_s[t] = g_bias[h * ND + (kb - q0 - 127 + t) + (SS - 1)];
        __syncthreads();

        // Q fragments for this tile (8 LDS.128, conflict-free)
        uint4 Aq0[4], Aq1[4];
#pragma unroll
        for (int u = 0; u < 4; u++) {
            Aq0[u] = *(const uint4*)&Qs[r0 * 68 + fc[u]];
            Aq1[u] = *(const uint4*)&Qs[r1 * 68 + fc[u]];
        }

        // S = Q @ K^T  (warp strip: 16 rows x 64 cols)
        float sv[8][4];
#pragma unroll
        for (int tn = 0; tn < 8; tn++)
#pragma unroll
            for (int c = 0; c < 4; c++) sv[tn][c] = 0.f;

#pragma unroll
        for (int tn = 0; tn < 8; tn++) {
            const int krow = (tn * 8 + g) * 68;
            float* d = sv[tn];
#pragma unroll
            for (int u = 0; u < 4; u++) {
                uint4 Kf = *(const uint4*)&Ks[krow + fc[u]];
                mma8(d[0], d[1], d[2], d[3],
                     Aq0[u].x, Aq1[u].x, Aq0[u].y, Aq1[u].y, Kf.x, Kf.y);  // kk = 16u
                mma8(d[0], d[1], d[2], d[3],
                     Aq0[u].z, Aq1[u].z, Aq0[u].w, Aq1[u].w, Kf.z, Kf.w);  // kk = 16u+8
            }
        }

        // bias + warp-local online softmax (rows r0, r1)
        float mx0 = -INFINITY, mx1 = -INFINITY;
#pragma unroll
        for (int tn = 0; tn < 8; tn++) {
            int c = tn * 8 + tig * 2;
            sv[tn][0] += bias_s[c - r0 + 127];
            sv[tn][1] += bias_s[c + 1 - r0 + 127];
            sv[tn][2] += bias_s[c - r1 + 127];
            sv[tn][3] += bias_s[c + 1 - r1 + 127];
            mx0 = fmaxf(mx0, fmaxf(sv[tn][0], sv[tn][1]));
            mx1 = fmaxf(mx1, fmaxf(sv[tn][2], sv[tn][3]));
        }
        mx0 = fmaxf(mx0, __shfl_xor_sync(0xffffffffu, mx0, 1));
        mx0 = fmaxf(mx0, __shfl_xor_sync(0xffffffffu, mx0, 2));
        mx1 = fmaxf(mx1, __shfl_xor_sync(0xffffffffu, mx1, 1));
        mx1 = fmaxf(mx1, __shfl_xor_sync(0xffffffffu, mx1, 2));
        const float mn0 = fmaxf(m0, mx0), mn1 = fmaxf(m1, mx1);
        const float sc0 = __expf(m0 - mn0), sc1 = __expf(m1 - mn1);
        float s0 = 0.f, s1 = 0.f;
#pragma unroll
        for (int tn = 0; tn < 8; tn++) {
            sv[tn][0] = __expf(sv[tn][0] - mn0);
            sv[tn][1] = __expf(sv[tn][1] - mn0);
            sv[tn][2] = __expf(sv[tn][2] - mn1);
            sv[tn][3] = __expf(sv[tn][3] - mn1);
            s0 += sv[tn][0] + sv[tn][1];
            s1 += sv[tn][2] + sv[tn][3];
        }
        s0 += __shfl_xor_sync(0xffffffffu, s0, 1);
        s0 += __shfl_xor_sync(0xffffffffu, s0, 2);
        s1 += __shfl_xor_sync(0xffffffffu, s1, 1);
        s1 += __shfl_xor_sync(0xffffffffu, s1, 2);
        l0 = l0 * sc0 + s0; l1 = l1 * sc1 + s1;
        m0 = mn0; m1 = mn1;

        // rescale O, spill P (warp-private rows -> only __syncwarp needed)
#pragma unroll
        for (int tn = 0; tn < 8; tn++) {
            oacc[tn][0] *= sc0; oacc[tn][1] *= sc0;
            oacc[tn][2] *= sc1; oacc[tn][3] *= sc1;
            int c = tn * 8 + tig * 2;
            Ps[(c)     * 140 + r0] = f2tf(sv[tn][0]);
            Ps[(c + 1) * 140 + r0] = f2tf(sv[tn][1]);
            Ps[(c)     * 140 + r1] = f2tf(sv[tn][2]);
            Ps[(c + 1) * 140 + r1] = f2tf(sv[tn][3]);
        }
        __syncwarp();

        // O += P @ V
#pragma unroll
        for (int c0 = 0; c0 < 64; c0 += 8) {
            unsigned a0 = Ps[(c0 + tig) * 140 + r0];
            unsigned a1 = Ps[(c0 + tig) * 140 + r1];
            unsigned a2 = Ps[(c0 + tig + 4) * 140 + r0];
            unsigned a3 = Ps[(c0 + tig + 4) * 140 + r1];
#pragma unroll
            for (int tn = 0; tn < 8; tn++) {
                unsigned bf0 = Vs[(c0 + tig) * 72 + tn * 8 + g];
                unsigned bf1 = Vs[(c0 + tig + 4) * 72 + tn * 8 + g];
                mma8(oacc[tn][0], oacc[tn][1], oacc[tn][2], oacc[tn][3],
                     a0, a1, a2, a3, bf0, bf1);
            }
        }
    }

    // Normalize + write ctx as PERMUTED tf32 bits into g_ctxp [B*S, 1024].
    // col = h*64 + n; within its 32-block: perm(c) = 16(tig&1)+2(tn&3)+(tig>>1),
    // and perm(c+1) = perm(c) + 8. Both stores land in the same 128B sector.
    const float i0 = 1.f / l0, i1 = 1.f / l1;
    unsigned* op = g_ctxp + ((size_t)(b_ * SS + q0)) * DD + h * DK;
#pragma unroll
    for (int tn = 0; tn < 8; tn++) {
        const int pb = 32 * (tn >> 2) + 16 * (tig & 1) + 2 * (tn & 3) + (tig >> 1);
        unsigned* o0 = op + (size_t)(rb + g) * DD + pb;
        unsigned* o1 = op + (size_t)(rb + g + 8) * DD + pb;
        o0[0] = f2tf(oacc[tn][0] * i0);
        o0[8] = f2tf(oacc[tn][1] * i0);
        o1[0] = f2tf(oacc[tn][2] * i1);
        o1[8] = f2tf(oacc[tn][3] * i1);
    }
}

// ---------------------------------------------------------------------------
extern "C" void kernel_launch(void* const* d_in, const int* in_sizes, int n_in,
                              void* d_out, int out_size) {
    const float* x        = (const float*)d_in[0];
    const float* q_w      = (const float*)d_in[1];
    const float* k_w      = (const float*)d_in[2];
    const float* v_w      = (const float*)d_in[3];
    const float* o_w      = (const float*)d_in[4];
    const float* rel_bias = (const float*)d_in[5];

    float *qp, *kp, *vp;
    unsigned *xp, *wq, *wk, *wv, *wo, *cxp;
    cudaGetSymbolAddress((void**)&qp, g_q);
    cudaGetSymbolAddress((void**)&kp, g_k);
    cudaGetSymbolAddress((void**)&vp, g_v);
    cudaGetSymbolAddress((void**)&xp, g_xp);
    cudaGetSymbolAddress((void**)&wq, g_wq);
    cudaGetSymbolAddress((void**)&wk, g_wk);
    cudaGetSymbolAddress((void**)&wv, g_wv);
    cudaGetSymbolAddress((void**)&wo, g_wo);
    cudaGetSymbolAddress((void**)&cxp, g_ctxp);

    bias_precompute<<<(ND + 255) / 256, 256>>>(rel_bias);
    prep_permute<<<MM, 256>>>(x, xp);          // 4096 rows
    prep_permute<<<DD, 256>>>(q_w, wq);        // 1024 rows each
    prep_permute<<<DD, 256>>>(k_w, wk);
    prep_permute<<<DD, 256>>>(v_w, wv);
    prep_permute<<<DD, 256>>>(o_w, wo);

    const int gemm_smem = 2 * 2 * 128 * 40 * 4;   // 81920 B
    cudaFuncSetAttribute(gemm_tf32<1>, cudaFuncAttributeMaxDynamicSharedMemorySize, gemm_smem);
    cudaFuncSetAttribute(gemm_tf32<0>, cudaFuncAttributeMaxDynamicSharedMemorySize, gemm_smem);

    // Fused QKV projection: grid.z picks the weight/output pair
    gemm_tf32<1><<<dim3(8, 32, 3), 256, gemm_smem>>>(xp, wq, wk, wv, qp, kp, vp);

    const size_t smem = (size_t)(128 * 68 + 64 * 140 + 64 * 68 + 64 * 72 + 192) * 4;
    cudaFuncSetAttribute(attn_tf32, cudaFuncAttributeMaxDynamicSharedMemorySize, (int)smem);
    attn_tf32<<<dim3(SS / 128, BB * HH), 256, smem>>>();

    // Output projection
    gemm_tf32<0><<<dim3(8, 32, 1), 256, gemm_smem>>>(cxp, wo, wo, wo,
                                                     (float*)d_out, (float*)d_out, (float*)d_out);
}

// round 17
// speedup vs baseline: 1.2726x; 1.2394x over previous
#include <cuda_runtime.h>
#include <cuda_fp16.h>
#include <math.h>

// Problem constants
#define BB 2
#define SS 2048
#define DD 1024
#define HH 16
#define DK 64
#define ND (2*SS-1)          // 4095 relative-distance slots
#define MM (BB*SS)           // 4096 rows in the GEMMs

// Scratch (allocation-free: __device__ globals)
__device__ float    g_q[BB*HH*SS*DK];     // [B,H,S,DK]
__device__ float    g_k[BB*HH*SS*DK];
__device__ float    g_v[BB*HH*SS*DK];
__device__ unsigned g_xp[MM*512];         // x, half2 units, perm32 blocks
__device__ unsigned g_wq[DD*512];         // weights, half2 units, perm32 blocks
__device__ unsigned g_wk[DD*512];
__device__ unsigned g_wv[DD*512];
__device__ unsigned g_wo[DD*512];
__device__ unsigned g_ctxp[MM*512];       // attention output, half2 units, perm32
__device__ float    g_bias[HH*ND];        // [H, rel+S-1]

// ---------------------------------------------------------------------------
// Helpers
// ---------------------------------------------------------------------------
__device__ __forceinline__ unsigned f2tf(float x) {
    unsigned u;
    asm("cvt.rna.tf32.f32 %0, %1;" : "=r"(u) : "f"(x));
    return u;
}

__device__ __forceinline__ unsigned f2h2(float lo, float hi) {
    __half2 h = __floats2half2_rn(lo, hi);
    return *(unsigned*)&h;
}

// tf32 k8 mma (attention path — proven)
__device__ __forceinline__ void mma8(float& d0, float& d1, float& d2, float& d3,
                                     unsigned a0, unsigned a1, unsigned a2, unsigned a3,
                                     unsigned b0, unsigned b1) {
    asm volatile("mma.sync.aligned.m16n8k8.row.col.f32.tf32.tf32.f32 "
                 "{%0,%1,%2,%3},{%4,%5,%6,%7},{%8,%9},{%0,%1,%2,%3};"
                 : "+f"(d0), "+f"(d1), "+f"(d2), "+f"(d3)
                 : "r"(a0), "r"(a1), "r"(a2), "r"(a3), "r"(b0), "r"(b1));
}

// f16 k16 mma (GEMM path — 2x FLOP per instruction, same 11-bit significand)
__device__ __forceinline__ void mma16(float& d0, float& d1, float& d2, float& d3,
                                      unsigned a0, unsigned a1, unsigned a2, unsigned a3,
                                      unsigned b0, unsigned b1) {
    asm volatile("mma.sync.aligned.m16n8k16.row.col.f32.f16.f16.f32 "
                 "{%0,%1,%2,%3},{%4,%5,%6,%7},{%8,%9},{%0,%1,%2,%3};"
                 : "+f"(d0), "+f"(d1), "+f"(d2), "+f"(d3)
                 : "r"(a0), "r"(a1), "r"(a2), "r"(a3), "r"(b0), "r"(b1));
}

__device__ __forceinline__ int qperm(int c) {
    int cp = (c & 3) * 16 + (c >> 2);
    return cp ^ (((c & 3) >> 1) * 8);
}

__device__ __forceinline__ unsigned smem_u32(const void* p) {
    unsigned r;
    asm("{ .reg .u64 t; cvta.to.shared.u64 t, %1; cvt.u32.u64 %0, t; }"
        : "=r"(r) : "l"(p));
    return r;
}

__device__ __forceinline__ void cpa16(unsigned dst, const void* src) {
    asm volatile("cp.async.cg.shared.global [%0], [%1], 16;" :: "r"(dst), "l"(src));
}

// ---------------------------------------------------------------------------
// Prep: fp32 -> half2 units, permuted within each 32-unit (64-element) block:
// in-block unit u -> position (u&3)*8 + (u>>2). One float4 (= 2 units) / thread.
// ---------------------------------------------------------------------------
__device__ __forceinline__ void prep_row(const float* __restrict__ src,
                                         unsigned* __restrict__ dst,
                                         int row, int c) {
    float4 v = *(const float4*)(src + (size_t)row * 1024 + c);
    int blk = (c >> 6) * 32;
    int u = (c & 63) >> 1;                  // even
    int p0 = (u & 3) * 8 + (u >> 2);        // u&3 in {0,2}; u+1 -> p0+8
    unsigned* d = dst + (size_t)row * 512 + blk;
    d[p0]     = f2h2(v.x, v.y);
    d[p0 + 8] = f2h2(v.z, v.w);
}

__global__ void prep_h2(const float* __restrict__ src, unsigned* __restrict__ dst) {
    prep_row(src, dst, blockIdx.x, threadIdx.x * 4);
}

__global__ void prep_h2_w4(const float* __restrict__ s0, const float* __restrict__ s1,
                           const float* __restrict__ s2, const float* __restrict__ s3,
                           unsigned* __restrict__ d0, unsigned* __restrict__ d1,
                           unsigned* __restrict__ d2, unsigned* __restrict__ d3) {
    int y = blockIdx.y;
    const float* s = (y == 0) ? s0 : (y == 1) ? s1 : (y == 2) ? s2 : s3;
    unsigned* d = (y == 0) ? d0 : (y == 1) ? d1 : (y == 2) ? d2 : d3;
    prep_row(s, d, blockIdx.x, threadIdx.x * 4);
}

// ---------------------------------------------------------------------------
// Bias precompute (correctness-proven)
// ---------------------------------------------------------------------------
__global__ void bias_precompute(const float* __restrict__ rel_bias) {
    int idx = blockIdx.x * blockDim.x + threadIdx.x;
    if (idx >= ND) return;
    int rel = idx - (SS - 1);
    int n = -rel;
    int ret = (n < 0) ? 16 : 0;
    n = (n < 0) ? -n : n;
    int bucket;
    if (n < 8) {
        bucket = n;
    } else {
        double v = log((double)n / 8.0) / log(16.0) * 8.0;
        int vi = 8 + (int)v;
        bucket = (vi < 15) ? vi : 15;
    }
    bucket += ret;
#pragma unroll
    for (int h = 0; h < HH; h++)
        g_bias[h * ND + idx] = rel_bias[bucket * HH + h];
}

// ---------------------------------------------------------------------------
// FP16 tensor-core GEMM (NT) over PRE-PERMUTED half2 inputs.
// C[m,n] = sum_k A[m,k]*B[n,k], fp32 accumulate. 128x128 tile, K=1024 staged
// as 16 chunks of 64 elements (32 half2 units/row), cp.async double-buffered.
// Fragment addressing identical to the proven tf32 layout (stride 40 units,
// chunk swizzle j^(r&1), ca = tig*8 ^ 4(g&1)); each uint4 A-load now feeds
// TWO m16n8k16 steps. Two CTAs co-resident.
// MODE 0: C row-major [M,N]; MODE 1: C as [B,H,S,DK] (fused head split).
// ---------------------------------------------------------------------------
template <int MODE>
__global__ __launch_bounds__(256, 2) void gemm_f16(
        const unsigned* __restrict__ A,
        const unsigned* __restrict__ B0p, const unsigned* __restrict__ B1p,
        const unsigned* __restrict__ B2p,
        float* __restrict__ C0p, float* __restrict__ C1p, float* __restrict__ C2p) {
    extern __shared__ unsigned smem[];      // [2 stages][A|B][128*40]
    const int STG = 128 * 40;
    const int t = threadIdx.x, lane = t & 31, g = lane >> 2, tig = lane & 3;
    const int w = t >> 5, wm = w >> 2, wn = w & 3;
    const int bm = blockIdx.y * 128, bn = blockIdx.x * 128;
    const int z = blockIdx.z;
    const unsigned* Bm = (z == 0) ? B0p : (z == 1) ? B1p : B2p;
    float* C = (z == 0) ? C0p : (z == 1) ? C1p : C2p;

    float acc[4][4][4];
#pragma unroll
    for (int a = 0; a < 4; a++)
#pragma unroll
        for (int b = 0; b < 4; b++)
#pragma unroll
            for (int c = 0; c < 4; c++) acc[a][b][c] = 0.f;

    // staging: 1024 16B-chunks per matrix per stage, 4 per thread
    int srow[4], sj[4]; unsigned sdo[4];
#pragma unroll
    for (int i = 0; i < 4; i++) {
        int lin = t + 256 * i;
        srow[i] = lin >> 3;
        sj[i]   = lin & 7;
        sdo[i]  = (unsigned)(srow[i] * 40 + ((sj[i] ^ (srow[i] & 1)) * 4)) * 4u;
    }
    const unsigned smb = smem_u32(smem);

#define STAGE(tile, st) do {                                                    \
        unsigned ab = smb + (unsigned)(st) * 2u * STG * 4u;                     \
        unsigned bb = ab + (unsigned)STG * 4u;                                  \
        int k0 = (tile) * 32;                                                   \
        _Pragma("unroll")                                                       \
        for (int i = 0; i < 4; i++) {                                           \
            cpa16(ab + sdo[i], A  + (size_t)(bm + srow[i]) * 512 + k0 + sj[i] * 4); \
            cpa16(bb + sdo[i], Bm + (size_t)(bn + srow[i]) * 512 + k0 + sj[i] * 4); \
        }                                                                       \
        asm volatile("cp.async.commit_group;");                                 \
    } while (0)

    STAGE(0, 0);
    STAGE(1, 1);

    const int sw  = (g & 1) * 4;
    const int ca0 = (tig * 8) ^ sw;       // units for k16-steps 0,1
    const int ca1 = (tig * 8 + 4) ^ sw;   // units for k16-steps 2,3

    for (int it = 0; it < 16; it++) {
        if (it < 15) asm volatile("cp.async.wait_group 1;" ::: "memory");
        else         asm volatile("cp.async.wait_group 0;" ::: "memory");
        __syncthreads();
        const unsigned* As = smem + (it & 1) * 2 * STG;
        const unsigned* Bs = As + STG;

        uint4 Bf0[4], Bf1[4];
#pragma unroll
        for (int tn = 0; tn < 4; tn++) {
            const int c = wn * 32 + tn * 8 + g;    // c&1 == g&1
            Bf0[tn] = *(const uint4*)&Bs[c * 40 + ca0];
            Bf1[tn] = *(const uint4*)&Bs[c * 40 + ca1];
        }
#pragma unroll
        for (int tm = 0; tm < 4; tm++) {
            const int r = wm * 64 + tm * 16 + g;   // r&1 == g&1
            uint4 A00 = *(const uint4*)&As[r * 40 + ca0];
            uint4 A01 = *(const uint4*)&As[r * 40 + ca1];
            uint4 A10 = *(const uint4*)&As[(r + 8) * 40 + ca0];
            uint4 A11 = *(const uint4*)&As[(r + 8) * 40 + ca1];
#pragma unroll
            for (int tn = 0; tn < 4; tn++) {
                float* d = acc[tm][tn];
                mma16(d[0], d[1], d[2], d[3], A00.x, A10.x, A00.y, A10.y, Bf0[tn].x, Bf0[tn].y); // k 0-15
                mma16(d[0], d[1], d[2], d[3], A00.z, A10.z, A00.w, A10.w, Bf0[tn].z, Bf0[tn].w); // k 16-31
                mma16(d[0], d[1], d[2], d[3], A01.x, A11.x, A01.y, A11.y, Bf1[tn].x, Bf1[tn].y); // k 32-47
                mma16(d[0], d[1], d[2], d[3], A01.z, A11.z, A01.w, A11.w, Bf1[tn].z, Bf1[tn].w); // k 48-63
            }
        }
        __syncthreads();
        if (it < 14) STAGE(it + 2, it & 1);
    }
#undef STAGE

#pragma unroll
    for (int tm = 0; tm < 4; tm++) {
#pragma unroll
        for (int tn = 0; tn < 4; tn++) {
            int m = bm + wm * 64 + tm * 16 + g;
            int n = bn + wn * 32 + tn * 8 + tig * 2;
            float2 v0 = make_float2(acc[tm][tn][0], acc[tm][tn][1]);
            float2 v1 = make_float2(acc[tm][tn][2], acc[tm][tn][3]);
            if (MODE == 0) {
                *(float2*)&C[(size_t)m * 1024 + n] = v0;
                *(float2*)&C[(size_t)(m + 8) * 1024 + n] = v1;
            } else {
                int h = n >> 6, dk = n & 63;
                int b0_ = m >> 11, s0 = m & 2047;
                *(float2*)&C[(((size_t)(b0_ * HH + h)) * SS + s0) * DK + dk] = v0;
                *(float2*)&C[(((size_t)(b0_ * HH + h)) * SS + s0 + 8) * DK + dk] = v1;
            }
        }
    }
}

// ---------------------------------------------------------------------------
// Flash attention with TF32 mma — the proven R10/R14 structure.
// Epilogue writes ctx as PERMUTED half2 units (g_ctxp) so the fp16
// output-projection GEMM consumes it with no conversion.
// ---------------------------------------------------------------------------
__global__ __launch_bounds__(256, 2) void attn_tf32() {
    extern __shared__ unsigned smu[];
    unsigned* Qs = smu;                   // [128][68]  permuted
    unsigned* Ps = Qs + 128 * 68;         // [64][140]
    unsigned* Ks = Ps + 64 * 140;         // [64][68]   permuted
    unsigned* Vs = Ks + 64 * 68;          // [64][72]   row-major
    float* bias_s = (float*)(Vs + 64 * 72);   // [192] (191 used)

    const int t = threadIdx.x, lane = t & 31, g = lane >> 2, tig = lane & 3;
    const int w = t >> 5;
    const int bh = blockIdx.y, h = bh & 15, b_ = bh >> 4;
    const int q0 = blockIdx.x * 128;
    const float* qg = g_q + (size_t)bh * SS * DK;
    const float* kg = g_k + (size_t)bh * SS * DK;
    const float* vg = g_v + (size_t)bh * SS * DK;

#pragma unroll
    for (int i = 0; i < 8; i++) {
        int lin = t + 256 * i;
        int r = lin >> 4, a = lin & 15;
        float4 v = *(const float4*)(qg + (size_t)(q0 + r) * DK + a * 4);
        unsigned* qr = &Qs[r * 68];
        qr[qperm(4 * a + 0)] = f2tf(v.x);
        qr[qperm(4 * a + 1)] = f2tf(v.y);
        qr[qperm(4 * a + 2)] = f2tf(v.z);
        qr[qperm(4 * a + 3)] = f2tf(v.w);
    }

    const int rb = w * 16;
    const int r0 = rb + g, r1 = rb + g + 8;

    const int fc[4] = { (tig * 16 + 0)  ^ ((tig >> 1) * 8),
                        (tig * 16 + 4)  ^ ((tig >> 1) * 8),
                        (tig * 16 + 8)  ^ ((tig >> 1) * 8),
                        (tig * 16 + 12) ^ ((tig >> 1) * 8) };

    float oacc[8][4];
#pragma unroll
    for (int tn = 0; tn < 8; tn++)
#pragma unroll
        for (int c = 0; c < 4; c++) oacc[tn][c] = 0.f;
    float m0 = -INFINITY, m1 = -INFINITY, l0 = 0.f, l1 = 0.f;

    for (int kt = 0; kt < SS / 64; kt++) {
        const int kb = kt * 64;
        __syncthreads();
#pragma unroll
        for (int i = 0; i < 4; i++) {
            int lin = t + 256 * i;
            int c = lin >> 4, a = lin & 15;
            float4 kv = *(const float4*)(kg + (size_t)(kb + c) * DK + a * 4);
            float4 vv = *(const float4*)(vg + (size_t)(kb + c) * DK + a * 4);
            unsigned* kr = &Ks[c * 68];
            kr[qperm(4 * a + 0)] = f2tf(kv.x);
            kr[qperm(4 * a + 1)] = f2tf(kv.y);
            kr[qperm(4 * a + 2)] = f2tf(kv.z);
            kr[qperm(4 * a + 3)] = f2tf(kv.w);
            *(uint4*)&Vs[c * 72 + a * 4] =
                make_uint4(f2tf(vv.x), f2tf(vv.y), f2tf(vv.z), f2tf(vv.w));
        }
        if (t < 191)
            bias_s[t] = g_bias[h * ND + (kb - q0 - 127 + t) + (SS - 1)];
        __syncthreads();

        uint4 Aq0[4], Aq1[4];
#pragma unroll
        for (int u = 0; u < 4; u++) {
            Aq0[u] = *(const uint4*)&Qs[r0 * 68 + fc[u]];
            Aq1[u] = *(const uint4*)&Qs[r1 * 68 + fc[u]];
        }

        float sv[8][4];
#pragma unroll
        for (int tn = 0; tn < 8; tn++)
#pragma unroll
            for (int c = 0; c < 4; c++) sv[tn][c] = 0.f;

#pragma unroll
        for (int tn = 0; tn < 8; tn++) {
            const int krow = (tn * 8 + g) * 68;
            float* d = sv[tn];
#pragma unroll
            for (int u = 0; u < 4; u++) {
                uint4 Kf = *(const uint4*)&Ks[krow + fc[u]];
                mma8(d[0], d[1], d[2], d[3],
                     Aq0[u].x, Aq1[u].x, Aq0[u].y, Aq1[u].y, Kf.x, Kf.y);
                mma8(d[0], d[1], d[2], d[3],
                     Aq0[u].z, Aq1[u].z, Aq0[u].w, Aq1[u].w, Kf.z, Kf.w);
            }
        }

        float mx0 = -INFINITY, mx1 = -INFINITY;
#pragma unroll
        for (int tn = 0; tn < 8; tn++) {
            int c = tn * 8 + tig * 2;
            sv[tn][0] += bias_s[c - r0 + 127];
            sv[tn][1] += bias_s[c + 1 - r0 + 127];
            sv[tn][2] += bias_s[c - r1 + 127];
            sv[tn][3] += bias_s[c + 1 - r1 + 127];
            mx0 = fmaxf(mx0, fmaxf(sv[tn][0], sv[tn][1]));
            mx1 = fmaxf(mx1, fmaxf(sv[tn][2], sv[tn][3]));
        }
        mx0 = fmaxf(mx0, __shfl_xor_sync(0xffffffffu, mx0, 1));
        mx0 = fmaxf(mx0, __shfl_xor_sync(0xffffffffu, mx0, 2));
        mx1 = fmaxf(mx1, __shfl_xor_sync(0xffffffffu, mx1, 1));
        mx1 = fmaxf(mx1, __shfl_xor_sync(0xffffffffu, mx1, 2));
        const float mn0 = fmaxf(m0, mx0), mn1 = fmaxf(m1, mx1);
        const float sc0 = __expf(m0 - mn0), sc1 = __expf(m1 - mn1);
        float s0 = 0.f, s1 = 0.f;
#pragma unroll
        for (int tn = 0; tn < 8; tn++) {
            sv[tn][0] = __expf(sv[tn][0] - mn0);
            sv[tn][1] = __expf(sv[tn][1] - mn0);
            sv[tn][2] = __expf(sv[tn][2] - mn1);
            sv[tn][3] = __expf(sv[tn][3] - mn1);
            s0 += sv[tn][0] + sv[tn][1];
            s1 += sv[tn][2] + sv[tn][3];
        }
        s0 += __shfl_xor_sync(0xffffffffu, s0, 1);
        s0 += __shfl_xor_sync(0xffffffffu, s0, 2);
        s1 += __shfl_xor_sync(0xffffffffu, s1, 1);
        s1 += __shfl_xor_sync(0xffffffffu, s1, 2);
        l0 = l0 * sc0 + s0; l1 = l1 * sc1 + s1;
        m0 = mn0; m1 = mn1;

#pragma unroll
        for (int tn = 0; tn < 8; tn++) {
            oacc[tn][0] *= sc0; oacc[tn][1] *= sc0;
            oacc[tn][2] *= sc1; oacc[tn][3] *= sc1;
            int c = tn * 8 + tig * 2;
            Ps[(c)     * 140 + r0] = f2tf(sv[tn][0]);
            Ps[(c + 1) * 140 + r0] = f2tf(sv[tn][1]);
            Ps[(c)     * 140 + r1] = f2tf(sv[tn][2]);
            Ps[(c + 1) * 140 + r1] = f2tf(sv[tn][3]);
        }
        __syncwarp();

#pragma unroll
        for (int c0 = 0; c0 < 64; c0 += 8) {
            unsigned a0 = Ps[(c0 + tig) * 140 + r0];
            unsigned a1 = Ps[(c0 + tig) * 140 + r1];
            unsigned a2 = Ps[(c0 + tig + 4) * 140 + r0];
            unsigned a3 = Ps[(c0 + tig + 4) * 140 + r1];
#pragma unroll
            for (int tn = 0; tn < 8; tn++) {
                unsigned bf0 = Vs[(c0 + tig) * 72 + tn * 8 + g];
                unsigned bf1 = Vs[(c0 + tig + 4) * 72 + tn * 8 + g];
                mma8(oacc[tn][0], oacc[tn][1], oacc[tn][2], oacc[tn][3],
                     a0, a1, a2, a3, bf0, bf1);
            }
        }
    }

    // Normalize + write ctx as permuted half2 units into g_ctxp [B*S, 512].
    // Cols n=8tn+2tig, n+1 form unit u=4tn+tig -> position tig*8+tn in head
    // block h (32 units). Thread's 8 stores span 32B in one 128B sector.
    const float i0 = 1.f / l0, i1 = 1.f / l1;
    unsigned* op = g_ctxp + ((size_t)(b_ * SS + q0)) * 512 + h * 32;
#pragma unroll
    for (int tn = 0; tn < 8; tn++) {
        const int p = tig * 8 + tn;
        op[(size_t)(rb + g) * 512 + p] =
            f2h2(oacc[tn][0] * i0, oacc[tn][1] * i0);
        op[(size_t)(rb + g + 8) * 512 + p] =
            f2h2(oacc[tn][2] * i1, oacc[tn][3] * i1);
    }
}

// ---------------------------------------------------------------------------
extern "C" void kernel_launch(void* const* d_in, const int* in_sizes, int n_in,
                              void* d_out, int out_size) {
    const float* x        = (const float*)d_in[0];
    const float* q_w      = (const float*)d_in[1];
    const float* k_w      = (const float*)d_in[2];
    const float* v_w      = (const float*)d_in[3];
    const float* o_w      = (const float*)d_in[4];
    const float* rel_bias = (const float*)d_in[5];

    float *qp, *kp, *vp;
    unsigned *xp, *wq, *wk, *wv, *wo, *cxp;
    cudaGetSymbolAddress((void**)&qp, g_q);
    cudaGetSymbolAddress((void**)&kp, g_k);
    cudaGetSymbolAddress((void**)&vp, g_v);
    cudaGetSymbolAddress((void**)&xp, g_xp);
    cudaGetSymbolAddress((void**)&wq, g_wq);
    cudaGetSymbolAddress((void**)&wk, g_wk);
    cudaGetSymbolAddress((void**)&wv, g_wv);
    cudaGetSymbolAddress((void**)&wo, g_wo);
    cudaGetSymbolAddress((void**)&cxp, g_ctxp);

    bias_precompute<<<(ND + 255) / 256, 256>>>(rel_bias);
    prep_h2<<<MM, 256>>>(x, xp);
    prep_h2_w4<<<dim3(DD, 4), 256>>>(q_w, k_w, v_w, o_w, wq, wk, wv, wo);

    const int gemm_smem = 2 * 2 * 128 * 40 * 4;   // 81920 B
    cudaFuncSetAttribute(gemm_f16<1>, cudaFuncAttributeMaxDynamicSharedMemorySize, gemm_smem);
    cudaFuncSetAttribute(gemm_f16<0>, cudaFuncAttributeMaxDynamicSharedMemorySize, gemm_smem);

    // Fused QKV projection: grid.z picks the weight/output pair
    gemm_f16<1><<<dim3(8, 32, 3), 256, gemm_smem>>>(xp, wq, wk, wv, qp, kp, vp);

    const size_t smem = (size_t)(128 * 68 + 64 * 140 + 64 * 68 + 64 * 72 + 192) * 4;
    cudaFuncSetAttribute(attn_tf32, cudaFuncAttributeMaxDynamicSharedMemorySize, (int)smem);
    attn_tf32<<<dim3(SS / 128, BB * HH), 256, smem>>>();

    // Output projection (consumes attention's half2-permuted ctx directly)
    gemm_f16<0><<<dim3(8, 32, 1), 256, gemm_smem>>>(cxp, wo, wo, wo,
                                                    (float*)d_out, (float*)d_out, (float*)d_out);
}